// round 14
// baseline (speedup 1.0000x reference)
#include <cuda_runtime.h>
#include <cuda_fp16.h>
#include <cstdint>
#include <math.h>

#define NTOK  4096
#define HDIM  1024
#define IDIM  1024
#define NEXP  8
#define TOPK  4
#define GUDIM 2048

#define MT 128
#define NT 128
#define KT 64
#define NCHUNK 16
#define NSTAGE 3

#define FB_TILE  (128 * 72 * 2)               // 18432 B
#define FB_STAGE (2 * FB_TILE)                // 36864 B
#define SMEM_TOTAL (1024 + NSTAGE * FB_STAGE) // 111616 B -> 2 CTAs/SM (223232 <= 228KB)

// ---------------- device scratch ----------------------------------------------------
__device__ __align__(16) __half g_xh [(size_t)NTOK * HDIM];
__device__ __align__(16) __half g_w1h[(size_t)NEXP * GUDIM * HDIM];   // [e][n][k]
__device__ __align__(16) __half g_w2h[(size_t)NEXP * HDIM * IDIM];    // [e][n][k]
__device__ __align__(16) __half g_act[(size_t)NEXP * NTOK * IDIM];
__device__ __align__(16) __half g_ebuf[(size_t)NTOK * TOPK * HDIM];   // 32 MB fp16
__device__ int g_count[NEXP];
__device__ int g_assign[NEXP * NTOK];

// ---------------- helpers -----------------------------------------------------------
__device__ __forceinline__ uint32_t smem_u32(const void* p) {
    uint32_t a;
    asm("{ .reg .u64 t; cvta.to.shared.u64 t, %1; cvt.u32.u64 %0, t; }" : "=r"(a) : "l"(p));
    return a;
}

#define CPA16(dst, src)       asm volatile("cp.async.cg.shared.global [%0], [%1], 16;"     :: "r"(dst), "l"(src))
#define CPA16P(dst, src, sz)  asm volatile("cp.async.cg.shared.global [%0], [%1], 16, %2;" :: "r"(dst), "l"(src), "r"(sz))
#define CPA_COMMIT()          asm volatile("cp.async.commit_group;" ::: "memory")
#define CPA_WAIT(n)           asm volatile("cp.async.wait_group %0;" :: "n"(n) : "memory")

__device__ __forceinline__ void ldsm4(uint32_t& r0, uint32_t& r1, uint32_t& r2, uint32_t& r3,
                                      uint32_t addr) {
    asm volatile("ldmatrix.sync.aligned.m8n8.x4.shared.b16 {%0,%1,%2,%3}, [%4];"
                 : "=r"(r0), "=r"(r1), "=r"(r2), "=r"(r3) : "r"(addr));
}
__device__ __forceinline__ void mma16816(float* d, const uint32_t* a, uint32_t b0, uint32_t b1) {
    asm volatile("mma.sync.aligned.m16n8k16.row.col.f32.f16.f16.f32 "
                 "{%0,%1,%2,%3},{%4,%5,%6,%7},{%8,%9},{%0,%1,%2,%3};"
                 : "+f"(d[0]), "+f"(d[1]), "+f"(d[2]), "+f"(d[3])
                 : "r"(a[0]), "r"(a[1]), "r"(a[2]), "r"(a[3]), "r"(b0), "r"(b1));
}

// ---------------- utility kernels ---------------------------------------------------
// transpose-convert: s [z][K][N] fp32 -> d [z][N][K] fp16 (also zeroes g_count)
__global__ void cvt_t_kernel(const float* __restrict__ s, __half* __restrict__ d,
                             int K, int N) {
    __shared__ float t[32][33];
    int tx = threadIdx.x, ty = threadIdx.y;
    if (blockIdx.x == 0 && blockIdx.y == 0 && blockIdx.z == 0 && ty == 0 && tx < NEXP)
        g_count[tx] = 0;
    int n0 = blockIdx.x * 32, k0 = blockIdx.y * 32, z = blockIdx.z;
    const float* sp = s + (size_t)z * K * N;
    __half* dp = d + (size_t)z * K * N;
#pragma unroll
    for (int i = 0; i < 32; i += 8)
        t[ty + i][tx] = sp[(size_t)(k0 + ty + i) * N + n0 + tx];
    __syncthreads();
    int id = ty * 32 + tx;
#pragma unroll
    for (int j = 0; j < 2; j++) {
        int v = id + j * 256;
        int r = v >> 4;
        int c = v & 15;
        __half2 h = __floats2half2_rn(t[c * 2][r], t[c * 2 + 1][r]);
        *(__half2*)(dp + (size_t)(n0 + r) * K + k0 + c * 2) = h;
    }
}

// ---------------- fused x-convert + router: 1 warp/token ----------------------------
__global__ void xr_kernel(const float* __restrict__ x,
                          const float* __restrict__ rw,
                          const float* __restrict__ rb,
                          float* __restrict__ ew_out) {
    int warp = (blockIdx.x * blockDim.x + threadIdx.x) >> 5;
    int lane = threadIdx.x & 31;
    if (warp >= NTOK) return;
    const float4* xr = (const float4*)(x + (size_t)warp * HDIM);
    __half2* xh = (__half2*)(g_xh + (size_t)warp * HDIM);

    float acc[NEXP];
#pragma unroll
    for (int e = 0; e < NEXP; e++) acc[e] = 0.f;

#pragma unroll
    for (int it = 0; it < 8; it++) {
        float4 xv = xr[lane + it * 32];
        xh[(lane + it * 32) * 2]     = __floats2half2_rn(xv.x, xv.y);
        xh[(lane + it * 32) * 2 + 1] = __floats2half2_rn(xv.z, xv.w);
#pragma unroll
        for (int e = 0; e < NEXP; e++) {
            float4 rv = ((const float4*)(rw + e * HDIM))[lane + it * 32];
            acc[e] += xv.x * rv.x + xv.y * rv.y + xv.z * rv.z + xv.w * rv.w;
        }
    }
#pragma unroll
    for (int e = 0; e < NEXP; e++) {
#pragma unroll
        for (int off = 16; off; off >>= 1)
            acc[e] += __shfl_xor_sync(0xffffffffu, acc[e], off);
    }
    if (lane == 0) {
        float lg[NEXP];
#pragma unroll
        for (int e = 0; e < NEXP; e++) lg[e] = acc[e] + rb[e];
        int idx[TOPK]; float val[TOPK]; bool used[NEXP];
#pragma unroll
        for (int e = 0; e < NEXP; e++) used[e] = false;
        for (int k = 0; k < TOPK; k++) {
            float best = -INFINITY; int bi = 0;
            for (int e = 0; e < NEXP; e++)
                if (!used[e] && lg[e] > best) { best = lg[e]; bi = e; }
            used[bi] = true; idx[k] = bi; val[k] = best;
        }
        float m = val[0], s = 0.f, w[TOPK];
        for (int k = 0; k < TOPK; k++) { w[k] = expf(val[k] - m); s += w[k]; }
        float inv = 1.f / s;
        for (int k = 0; k < TOPK; k++) {
            w[k] *= inv;
            ew_out[warp * TOPK + k] = w[k];
            int p = atomicAdd(&g_count[idx[k]], 1);
            g_assign[idx[k] * NTOK + p] = warp * 4 + k;
        }
    }
}

// ====================================================================================
// GEMM1: act = SwiGLU(gather(x) @ w1^T + b1)   (128 thr, 4 warps, 3-stage pipeline)
// ====================================================================================
__global__ __launch_bounds__(128, 2)
void gemm1_kernel(const float* __restrict__ b1) {
    extern __shared__ char smem[];
    const int e    = blockIdx.z;
    const int cnt  = g_count[e];
    const int row0 = blockIdx.y * MT;
    if (row0 >= cnt) return;
    const int col0 = blockIdx.x * NT;
    const int tid = threadIdx.x, lane = tid & 31, wid = tid >> 5;
    const int wm = wid >> 1, wn = wid & 1;
    uint32_t sb = smem_u32(smem);
    int* s_tok = (int*)smem;

    {
        int r = row0 + tid;
        s_tok[tid] = (r < cnt) ? (g_assign[e * NTOK + r] >> 2) : -1;
    }
    __syncthreads();

    float d[4][8][4];
#pragma unroll
    for (int mi = 0; mi < 4; mi++)
#pragma unroll
        for (int nt = 0; nt < 8; nt++)
#pragma unroll
            for (int r = 0; r < 4; r++) d[mi][nt][r] = 0.f;

    const __half* Bb = g_w1h + ((size_t)e * GUDIM + col0) * HDIM;
    const int lr = tid >> 3, lc = tid & 7;

    auto issue = [&](int cidx) {
        int p = cidx % NSTAGE, kt = cidx * KT;
        uint32_t a0 = sb + 1024 + p * FB_STAGE;
        uint32_t b0 = a0 + FB_TILE;
#pragma unroll
        for (int i = 0; i < 8; i++) {
            int r = lr + i * 16;
            int tok = s_tok[r];
            CPA16P(a0 + (r * 72 + lc * 8) * 2,
                   g_xh + (size_t)(tok < 0 ? 0 : tok) * HDIM + kt + lc * 8,
                   (tok >= 0) ? 16 : 0);
            CPA16(b0 + (r * 72 + lc * 8) * 2, Bb + (size_t)r * HDIM + kt + lc * 8);
        }
        CPA_COMMIT();
    };

    issue(0);
    issue(1);
    for (int cc = 0; cc < NCHUNK; cc++) {
        int p = cc % NSTAGE;
        if (cc + 1 < NCHUNK) CPA_WAIT(1); else CPA_WAIT(0);
        __syncthreads();
        if (cc + 2 < NCHUNK) issue(cc + 2);
        uint32_t sA = sb + 1024 + p * FB_STAGE;
        uint32_t sB = sA + FB_TILE;
        uint32_t aBase = sA + ((wm * 64 + (lane & 15)) * 72 + (lane >> 4) * 8) * 2;
        uint32_t bBase = sB + ((wn * 64 + (lane & 7) + (lane >> 4) * 8) * 72 +
                               ((lane >> 3) & 1) * 8) * 2;
#pragma unroll
        for (int kk = 0; kk < KT; kk += 16) {
            uint32_t a[4][4], b[4][4];
#pragma unroll
            for (int mi = 0; mi < 4; mi++)
                ldsm4(a[mi][0], a[mi][1], a[mi][2], a[mi][3],
                      aBase + (mi * 16 * 72 + kk) * 2);
#pragma unroll
            for (int g = 0; g < 4; g++)
                ldsm4(b[g][0], b[g][1], b[g][2], b[g][3],
                      bBase + (g * 16 * 72 + kk) * 2);
#pragma unroll
            for (int mi = 0; mi < 4; mi++)
#pragma unroll
                for (int g = 0; g < 4; g++) {
                    mma16816(d[mi][2 * g],     a[mi], b[g][0], b[g][1]);
                    mma16816(d[mi][2 * g + 1], a[mi], b[g][2], b[g][3]);
                }
        }
    }
    __syncthreads();   // buffers become staging area

    // epilogue: SwiGLU from register pairs; stage fp16 [128 rows][64 cols] pitch 72
    __half* st_h = (__half*)(smem + 1024);
    const float* bb = b1 + e * GUDIM + col0;
#pragma unroll
    for (int mi = 0; mi < 4; mi++) {
        int rbase = wm * 64 + mi * 16 + (lane >> 2);
#pragma unroll
        for (int nt = 0; nt < 8; nt++) {
            int gcl = wn * 64 + nt * 8 + (lane & 3) * 2;
            float bg = bb[gcl], bu = bb[gcl + 1];
            int acl = (gcl >> 1);
#pragma unroll
            for (int h = 0; h < 2; h++) {
                float g = d[mi][nt][2 * h]     + bg;
                float u = d[mi][nt][2 * h + 1] + bu;
                g = fminf(g, 7.0f);
                u = fminf(fmaxf(u, -7.0f), 7.0f);
                float glu = g / (1.0f + expf(-1.702f * g));
                st_h[(rbase + 8 * h) * 72 + acl] = __float2half((u + 1.0f) * glu);
            }
        }
    }
    __syncthreads();
    {
        int rg = row0 + tid;
        if (rg < cnt) {
            __half* dst = g_act + ((size_t)e * NTOK + rg) * IDIM + (col0 >> 1);
            const __half* src = st_h + tid * 72;
#pragma unroll
            for (int j = 0; j < 8; j++)
                *(int4*)(dst + j * 8) = *(const int4*)(src + j * 8);
        }
    }
}

// ====================================================================================
// GEMM2: ebuf[assign] = fp16(act @ w2^T + b2)   (3-stage pipeline)
// ====================================================================================
__global__ __launch_bounds__(128, 2)
void gemm2_kernel(const float* __restrict__ b2) {
    extern __shared__ char smem[];
    const int e    = blockIdx.z;
    const int cnt  = g_count[e];
    const int row0 = blockIdx.y * MT;
    if (row0 >= cnt) return;
    const int col0 = blockIdx.x * NT;
    const int tid = threadIdx.x, lane = tid & 31, wid = tid >> 5;
    const int wm = wid >> 1, wn = wid & 1;
    uint32_t sb = smem_u32(smem);
    int* s_asn = (int*)smem;

    {
        int r = row0 + tid;
        s_asn[tid] = (r < cnt) ? g_assign[e * NTOK + r] : -1;
    }
    __syncthreads();

    float d[4][8][4];
#pragma unroll
    for (int mi = 0; mi < 4; mi++)
#pragma unroll
        for (int nt = 0; nt < 8; nt++)
#pragma unroll
            for (int r = 0; r < 4; r++) d[mi][nt][r] = 0.f;

    const __half* Ab = g_act + ((size_t)e * NTOK + row0) * IDIM;
    const __half* Bb = g_w2h + (size_t)e * HDIM * IDIM + (size_t)col0 * IDIM;
    const int lr = tid >> 3, lc = tid & 7;

    auto issue = [&](int cidx) {
        int p = cidx % NSTAGE, kt = cidx * KT;
        uint32_t a0 = sb + 1024 + p * FB_STAGE;
        uint32_t b0 = a0 + FB_TILE;
#pragma unroll
        for (int i = 0; i < 8; i++) {
            int r = lr + i * 16;
            int ok = (s_asn[r] >= 0) ? 16 : 0;
            CPA16P(a0 + (r * 72 + lc * 8) * 2, Ab + (size_t)r * IDIM + kt + lc * 8, ok);
            CPA16(b0 + (r * 72 + lc * 8) * 2, Bb + (size_t)r * IDIM + kt + lc * 8);
        }
        CPA_COMMIT();
    };

    issue(0);
    issue(1);
    for (int cc = 0; cc < NCHUNK; cc++) {
        int p = cc % NSTAGE;
        if (cc + 1 < NCHUNK) CPA_WAIT(1); else CPA_WAIT(0);
        __syncthreads();
        if (cc + 2 < NCHUNK) issue(cc + 2);
        uint32_t sA = sb + 1024 + p * FB_STAGE;
        uint32_t sB = sA + FB_TILE;
        uint32_t aBase = sA + ((wm * 64 + (lane & 15)) * 72 + (lane >> 4) * 8) * 2;
        uint32_t bBase = sB + ((wn * 64 + (lane & 7) + (lane >> 4) * 8) * 72 +
                               ((lane >> 3) & 1) * 8) * 2;
#pragma unroll
        for (int kk = 0; kk < KT; kk += 16) {
            uint32_t a[4][4], b[4][4];
#pragma unroll
            for (int mi = 0; mi < 4; mi++)
                ldsm4(a[mi][0], a[mi][1], a[mi][2], a[mi][3],
                      aBase + (mi * 16 * 72 + kk) * 2);
#pragma unroll
            for (int g = 0; g < 4; g++)
                ldsm4(b[g][0], b[g][1], b[g][2], b[g][3],
                      bBase + (g * 16 * 72 + kk) * 2);
#pragma unroll
            for (int mi = 0; mi < 4; mi++)
#pragma unroll
                for (int g = 0; g < 4; g++) {
                    mma16816(d[mi][2 * g],     a[mi], b[g][0], b[g][1]);
                    mma16816(d[mi][2 * g + 1], a[mi], b[g][2], b[g][3]);
                }
        }
    }

    // epilogue: bias + fp16 scatter to ebuf
    const float* bb = b2 + e * HDIM + col0;
#pragma unroll
    for (int mi = 0; mi < 4; mi++) {
        int rbase = wm * 64 + mi * 16 + (lane >> 2);
#pragma unroll
        for (int h = 0; h < 2; h++) {
            int rl = rbase + 8 * h;
            int a = s_asn[rl];
            if (a >= 0) {
                __half* dst = g_ebuf + (size_t)a * HDIM + col0;
#pragma unroll
                for (int nt = 0; nt < 8; nt++) {
                    int cl = wn * 64 + nt * 8 + (lane & 3) * 2;
                    *(__half2*)(dst + cl) =
                        __floats2half2_rn(d[mi][nt][2 * h]     + bb[cl],
                                          d[mi][nt][2 * h + 1] + bb[cl + 1]);
                }
            }
        }
    }
}

// ---------------- combine: out[t] = sum_k w[t][k] * ebuf[t*4+k] ---------------------
__global__ void combine_kernel(float* __restrict__ out) {
    const float* ew = out + (size_t)NTOK * HDIM;
    int stride = gridDim.x * blockDim.x;
    int n4 = NTOK * HDIM / 4;
    for (int v = blockIdx.x * blockDim.x + threadIdx.x; v < n4; v += stride) {
        int t  = v >> 8;
        int hc = v & 255;
        float w0 = ew[t * 4 + 0], w1v = ew[t * 4 + 1];
        float w2v = ew[t * 4 + 2], w3 = ew[t * 4 + 3];
        const __half* eb = g_ebuf + (size_t)t * 4 * HDIM + hc * 4;
        __half2 a0 = *(const __half2*)(eb);
        __half2 a1 = *(const __half2*)(eb + 2);
        __half2 b0 = *(const __half2*)(eb + HDIM);
        __half2 b1 = *(const __half2*)(eb + HDIM + 2);
        __half2 c0 = *(const __half2*)(eb + 2 * HDIM);
        __half2 c1 = *(const __half2*)(eb + 2 * HDIM + 2);
        __half2 d0 = *(const __half2*)(eb + 3 * HDIM);
        __half2 d1 = *(const __half2*)(eb + 3 * HDIM + 2);
        float2 fa0 = __half22float2(a0), fa1 = __half22float2(a1);
        float2 fb0 = __half22float2(b0), fb1 = __half22float2(b1);
        float2 fc0 = __half22float2(c0), fc1 = __half22float2(c1);
        float2 fd0 = __half22float2(d0), fd1 = __half22float2(d1);
        float4 o;
        o.x = w0 * fa0.x + w1v * fb0.x + w2v * fc0.x + w3 * fd0.x;
        o.y = w0 * fa0.y + w1v * fb0.y + w2v * fc0.y + w3 * fd0.y;
        o.z = w0 * fa1.x + w1v * fb1.x + w2v * fc1.x + w3 * fd1.x;
        o.w = w0 * fa1.y + w1v * fb1.y + w2v * fc1.y + w3 * fd1.y;
        ((float4*)out)[v] = o;
    }
}

// ---------------- launch ------------------------------------------------------------
extern "C" void kernel_launch(void* const* d_in, const int* in_sizes, int n_in,
                              void* d_out, int out_size) {
    const float* x  = (const float*)d_in[0];
    const float* rw = (const float*)d_in[1];
    const float* rb = (const float*)d_in[2];
    const float* w1 = (const float*)d_in[3];
    const float* b1 = (const float*)d_in[4];
    const float* w2 = (const float*)d_in[5];
    const float* b2 = (const float*)d_in[6];
    float* out = (float*)d_out;

    cudaFuncSetAttribute(gemm1_kernel, cudaFuncAttributeMaxDynamicSharedMemorySize, SMEM_TOTAL);
    cudaFuncSetAttribute(gemm2_kernel, cudaFuncAttributeMaxDynamicSharedMemorySize, SMEM_TOTAL);

    __half* w1h; cudaGetSymbolAddress((void**)&w1h, g_w1h);
    __half* w2h; cudaGetSymbolAddress((void**)&w2h, g_w2h);
    cvt_t_kernel<<<dim3(GUDIM / 32, HDIM / 32, NEXP), dim3(32, 8)>>>(w1, w1h, HDIM, GUDIM);
    cvt_t_kernel<<<dim3(HDIM / 32, IDIM / 32, NEXP), dim3(32, 8)>>>(w2, w2h, IDIM, HDIM);

    xr_kernel<<<NTOK / 8, 256>>>(x, rw, rb, out + (size_t)NTOK * HDIM);

    gemm1_kernel<<<dim3(GUDIM / NT, NTOK / MT, NEXP), 128, SMEM_TOTAL>>>(b1);
    gemm2_kernel<<<dim3(HDIM  / NT, NTOK / MT, NEXP), 128, SMEM_TOTAL>>>(b2);

    combine_kernel<<<2048, 256>>>(out);
}

// round 15
// speedup vs baseline: 1.0208x; 1.0208x over previous
#include <cuda_runtime.h>
#include <cuda_fp16.h>
#include <cstdint>
#include <math.h>

#define NTOK  4096
#define HDIM  1024
#define IDIM  1024
#define NEXP  8
#define TOPK  4
#define GUDIM 2048

#define MT 128
#define NT 128
#define KT 64
#define NCHUNK 16

#define FB_TILE  (128 * 72 * 2)          // 18432 B
#define FB_STAGE (2 * FB_TILE)           // 36864 B
#define SMEM_TOTAL (1024 + 2 * FB_STAGE) // 74752 B -> 2 CTAs/SM

// ---------------- device scratch ----------------------------------------------------
__device__ __align__(16) __half g_xh [(size_t)NTOK * HDIM];
__device__ __align__(16) __half g_w1h[(size_t)NEXP * GUDIM * HDIM];   // [e][n][k]
__device__ __align__(16) __half g_w2h[(size_t)NEXP * HDIM * IDIM];    // [e][n][k]
__device__ __align__(16) __half g_act[(size_t)NEXP * NTOK * IDIM];
__device__ __align__(16) __half g_ebuf[(size_t)NTOK * TOPK * HDIM];   // 32 MB fp16
__device__ int g_count[NEXP];
__device__ int g_assign[NEXP * NTOK];

// ---------------- helpers -----------------------------------------------------------
__device__ __forceinline__ uint32_t smem_u32(const void* p) {
    uint32_t a;
    asm("{ .reg .u64 t; cvta.to.shared.u64 t, %1; cvt.u32.u64 %0, t; }" : "=r"(a) : "l"(p));
    return a;
}

#define CPA16(dst, src)       asm volatile("cp.async.cg.shared.global [%0], [%1], 16;"     :: "r"(dst), "l"(src))
#define CPA16P(dst, src, sz)  asm volatile("cp.async.cg.shared.global [%0], [%1], 16, %2;" :: "r"(dst), "l"(src), "r"(sz))
#define CPA_COMMIT()          asm volatile("cp.async.commit_group;" ::: "memory")
#define CPA_WAIT(n)           asm volatile("cp.async.wait_group %0;" :: "n"(n) : "memory")

__device__ __forceinline__ void ldsm4(uint32_t& r0, uint32_t& r1, uint32_t& r2, uint32_t& r3,
                                      uint32_t addr) {
    asm volatile("ldmatrix.sync.aligned.m8n8.x4.shared.b16 {%0,%1,%2,%3}, [%4];"
                 : "=r"(r0), "=r"(r1), "=r"(r2), "=r"(r3) : "r"(addr));
}
__device__ __forceinline__ void mma16816(float* d, const uint32_t* a, uint32_t b0, uint32_t b1) {
    asm volatile("mma.sync.aligned.m16n8k16.row.col.f32.f16.f16.f32 "
                 "{%0,%1,%2,%3},{%4,%5,%6,%7},{%8,%9},{%0,%1,%2,%3};"
                 : "+f"(d[0]), "+f"(d[1]), "+f"(d[2]), "+f"(d[3])
                 : "r"(a[0]), "r"(a[1]), "r"(a[2]), "r"(a[3]), "r"(b0), "r"(b1));
}

// fragment load for one k-step (8 ldsm.x4)
#define LOAD_FRAGS(af, bf, aB, bB, kkv) do {                                  \
    _Pragma("unroll")                                                         \
    for (int mi = 0; mi < 4; mi++)                                            \
        ldsm4((af)[mi][0], (af)[mi][1], (af)[mi][2], (af)[mi][3],             \
              (aB) + (mi * 16 * 72 + (kkv)) * 2);                             \
    _Pragma("unroll")                                                         \
    for (int g = 0; g < 4; g++)                                               \
        ldsm4((bf)[g][0], (bf)[g][1], (bf)[g][2], (bf)[g][3],                 \
              (bB) + (g * 16 * 72 + (kkv)) * 2);                              \
} while (0)

#define DO_MMAS(df, af, bf) do {                                              \
    _Pragma("unroll")                                                         \
    for (int mi = 0; mi < 4; mi++)                                            \
        _Pragma("unroll")                                                     \
        for (int g = 0; g < 4; g++) {                                         \
            mma16816((df)[mi][2 * g],     (af)[mi], (bf)[g][0], (bf)[g][1]);  \
            mma16816((df)[mi][2 * g + 1], (af)[mi], (bf)[g][2], (bf)[g][3]);  \
        }                                                                     \
} while (0)

// ---------------- utility kernels ---------------------------------------------------
// transpose-convert: s [z][K][N] fp32 -> d [z][N][K] fp16 (also zeroes g_count)
__global__ void cvt_t_kernel(const float* __restrict__ s, __half* __restrict__ d,
                             int K, int N) {
    __shared__ float t[32][33];
    int tx = threadIdx.x, ty = threadIdx.y;
    if (blockIdx.x == 0 && blockIdx.y == 0 && blockIdx.z == 0 && ty == 0 && tx < NEXP)
        g_count[tx] = 0;
    int n0 = blockIdx.x * 32, k0 = blockIdx.y * 32, z = blockIdx.z;
    const float* sp = s + (size_t)z * K * N;
    __half* dp = d + (size_t)z * K * N;
#pragma unroll
    for (int i = 0; i < 32; i += 8)
        t[ty + i][tx] = sp[(size_t)(k0 + ty + i) * N + n0 + tx];
    __syncthreads();
    int id = ty * 32 + tx;
#pragma unroll
    for (int j = 0; j < 2; j++) {
        int v = id + j * 256;
        int r = v >> 4;
        int c = v & 15;
        __half2 h = __floats2half2_rn(t[c * 2][r], t[c * 2 + 1][r]);
        *(__half2*)(dp + (size_t)(n0 + r) * K + k0 + c * 2) = h;
    }
}

// ---------------- fused x-convert + router: 1 warp/token ----------------------------
__global__ void xr_kernel(const float* __restrict__ x,
                          const float* __restrict__ rw,
                          const float* __restrict__ rb,
                          float* __restrict__ ew_out) {
    int warp = (blockIdx.x * blockDim.x + threadIdx.x) >> 5;
    int lane = threadIdx.x & 31;
    if (warp >= NTOK) return;
    const float4* xr = (const float4*)(x + (size_t)warp * HDIM);
    __half2* xh = (__half2*)(g_xh + (size_t)warp * HDIM);

    float acc[NEXP];
#pragma unroll
    for (int e = 0; e < NEXP; e++) acc[e] = 0.f;

#pragma unroll
    for (int it = 0; it < 8; it++) {
        float4 xv = xr[lane + it * 32];
        xh[(lane + it * 32) * 2]     = __floats2half2_rn(xv.x, xv.y);
        xh[(lane + it * 32) * 2 + 1] = __floats2half2_rn(xv.z, xv.w);
#pragma unroll
        for (int e = 0; e < NEXP; e++) {
            float4 rv = ((const float4*)(rw + e * HDIM))[lane + it * 32];
            acc[e] += xv.x * rv.x + xv.y * rv.y + xv.z * rv.z + xv.w * rv.w;
        }
    }
#pragma unroll
    for (int e = 0; e < NEXP; e++) {
#pragma unroll
        for (int off = 16; off; off >>= 1)
            acc[e] += __shfl_xor_sync(0xffffffffu, acc[e], off);
    }
    if (lane == 0) {
        float lg[NEXP];
#pragma unroll
        for (int e = 0; e < NEXP; e++) lg[e] = acc[e] + rb[e];
        int idx[TOPK]; float val[TOPK]; bool used[NEXP];
#pragma unroll
        for (int e = 0; e < NEXP; e++) used[e] = false;
        for (int k = 0; k < TOPK; k++) {
            float best = -INFINITY; int bi = 0;
            for (int e = 0; e < NEXP; e++)
                if (!used[e] && lg[e] > best) { best = lg[e]; bi = e; }
            used[bi] = true; idx[k] = bi; val[k] = best;
        }
        float m = val[0], s = 0.f, w[TOPK];
        for (int k = 0; k < TOPK; k++) { w[k] = expf(val[k] - m); s += w[k]; }
        float inv = 1.f / s;
        for (int k = 0; k < TOPK; k++) {
            w[k] *= inv;
            ew_out[warp * TOPK + k] = w[k];
            int p = atomicAdd(&g_count[idx[k]], 1);
            g_assign[idx[k] * NTOK + p] = warp * 4 + k;
        }
    }
}

// ====================================================================================
// GEMM1: act = SwiGLU(gather(x) @ w1^T + b1)  (fragment double-buffered k-loop)
// ====================================================================================
__global__ __launch_bounds__(128, 2)
void gemm1_kernel(const float* __restrict__ b1) {
    extern __shared__ char smem[];
    const int e    = blockIdx.z;
    const int cnt  = g_count[e];
    const int row0 = blockIdx.y * MT;
    if (row0 >= cnt) return;
    const int col0 = blockIdx.x * NT;
    const int tid = threadIdx.x, lane = tid & 31, wid = tid >> 5;
    const int wm = wid >> 1, wn = wid & 1;
    uint32_t sb = smem_u32(smem);
    int* s_tok = (int*)smem;

    {
        int r = row0 + tid;
        s_tok[tid] = (r < cnt) ? (g_assign[e * NTOK + r] >> 2) : -1;
    }
    __syncthreads();

    float d[4][8][4];
#pragma unroll
    for (int mi = 0; mi < 4; mi++)
#pragma unroll
        for (int nt = 0; nt < 8; nt++)
#pragma unroll
            for (int r = 0; r < 4; r++) d[mi][nt][r] = 0.f;

    const __half* Bb = g_w1h + ((size_t)e * GUDIM + col0) * HDIM;
    const int lr = tid >> 3, lc = tid & 7;

    auto issue = [&](int cidx) {
        int p = cidx & 1, kt = cidx * KT;
        uint32_t a0 = sb + 1024 + p * FB_STAGE;
        uint32_t b0 = a0 + FB_TILE;
#pragma unroll
        for (int i = 0; i < 8; i++) {
            int r = lr + i * 16;
            int tok = s_tok[r];
            CPA16P(a0 + (r * 72 + lc * 8) * 2,
                   g_xh + (size_t)(tok < 0 ? 0 : tok) * HDIM + kt + lc * 8,
                   (tok >= 0) ? 16 : 0);
            CPA16(b0 + (r * 72 + lc * 8) * 2, Bb + (size_t)r * HDIM + kt + lc * 8);
        }
        CPA_COMMIT();
    };

    issue(0);
    for (int cc = 0; cc < NCHUNK; cc++) {
        int p = cc & 1;
        CPA_WAIT(0);
        __syncthreads();
        if (cc + 1 < NCHUNK) issue(cc + 1);
        uint32_t sA = sb + 1024 + p * FB_STAGE;
        uint32_t sB = sA + FB_TILE;
        uint32_t aBase = sA + ((wm * 64 + (lane & 15)) * 72 + (lane >> 4) * 8) * 2;
        uint32_t bBase = sB + ((wn * 64 + (lane & 7) + (lane >> 4) * 8) * 72 +
                               ((lane >> 3) & 1) * 8) * 2;

        uint32_t af0[4][4], bf0[4][4], af1[4][4], bf1[4][4];
        LOAD_FRAGS(af0, bf0, aBase, bBase, 0);
        LOAD_FRAGS(af1, bf1, aBase, bBase, 16);
        DO_MMAS(d, af0, bf0);
        LOAD_FRAGS(af0, bf0, aBase, bBase, 32);
        DO_MMAS(d, af1, bf1);
        LOAD_FRAGS(af1, bf1, aBase, bBase, 48);
        DO_MMAS(d, af0, bf0);
        DO_MMAS(d, af1, bf1);
    }
    __syncthreads();   // buffers become staging area

    // epilogue: SwiGLU from register pairs; stage fp16 [128 rows][64 cols] pitch 72
    __half* st_h = (__half*)(smem + 1024);
    const float* bb = b1 + e * GUDIM + col0;
#pragma unroll
    for (int mi = 0; mi < 4; mi++) {
        int rbase = wm * 64 + mi * 16 + (lane >> 2);
#pragma unroll
        for (int nt = 0; nt < 8; nt++) {
            int gcl = wn * 64 + nt * 8 + (lane & 3) * 2;
            float bg = bb[gcl], bu = bb[gcl + 1];
            int acl = (gcl >> 1);
#pragma unroll
            for (int h = 0; h < 2; h++) {
                float g = d[mi][nt][2 * h]     + bg;
                float u = d[mi][nt][2 * h + 1] + bu;
                g = fminf(g, 7.0f);
                u = fminf(fmaxf(u, -7.0f), 7.0f);
                float glu = g / (1.0f + expf(-1.702f * g));
                st_h[(rbase + 8 * h) * 72 + acl] = __float2half((u + 1.0f) * glu);
            }
        }
    }
    __syncthreads();
    {
        int rg = row0 + tid;
        if (rg < cnt) {
            __half* dst = g_act + ((size_t)e * NTOK + rg) * IDIM + (col0 >> 1);
            const __half* src = st_h + tid * 72;
#pragma unroll
            for (int j = 0; j < 8; j++)
                *(int4*)(dst + j * 8) = *(const int4*)(src + j * 8);
        }
    }
}

// ====================================================================================
// GEMM2: ebuf[assign] = fp16(act @ w2^T + b2)  (fragment double-buffered k-loop)
// ====================================================================================
__global__ __launch_bounds__(128, 2)
void gemm2_kernel(const float* __restrict__ b2) {
    extern __shared__ char smem[];
    const int e    = blockIdx.z;
    const int cnt  = g_count[e];
    const int row0 = blockIdx.y * MT;
    if (row0 >= cnt) return;
    const int col0 = blockIdx.x * NT;
    const int tid = threadIdx.x, lane = tid & 31, wid = tid >> 5;
    const int wm = wid >> 1, wn = wid & 1;
    uint32_t sb = smem_u32(smem);
    int* s_asn = (int*)smem;

    {
        int r = row0 + tid;
        s_asn[tid] = (r < cnt) ? g_assign[e * NTOK + r] : -1;
    }
    __syncthreads();

    float d[4][8][4];
#pragma unroll
    for (int mi = 0; mi < 4; mi++)
#pragma unroll
        for (int nt = 0; nt < 8; nt++)
#pragma unroll
            for (int r = 0; r < 4; r++) d[mi][nt][r] = 0.f;

    const __half* Ab = g_act + ((size_t)e * NTOK + row0) * IDIM;
    const __half* Bb = g_w2h + (size_t)e * HDIM * IDIM + (size_t)col0 * IDIM;
    const int lr = tid >> 3, lc = tid & 7;

    auto issue = [&](int cidx) {
        int p = cidx & 1, kt = cidx * KT;
        uint32_t a0 = sb + 1024 + p * FB_STAGE;
        uint32_t b0 = a0 + FB_TILE;
#pragma unroll
        for (int i = 0; i < 8; i++) {
            int r = lr + i * 16;
            int ok = (s_asn[r] >= 0) ? 16 : 0;
            CPA16P(a0 + (r * 72 + lc * 8) * 2, Ab + (size_t)r * IDIM + kt + lc * 8, ok);
            CPA16(b0 + (r * 72 + lc * 8) * 2, Bb + (size_t)r * IDIM + kt + lc * 8);
        }
        CPA_COMMIT();
    };

    issue(0);
    for (int cc = 0; cc < NCHUNK; cc++) {
        int p = cc & 1;
        CPA_WAIT(0);
        __syncthreads();
        if (cc + 1 < NCHUNK) issue(cc + 1);
        uint32_t sA = sb + 1024 + p * FB_STAGE;
        uint32_t sB = sA + FB_TILE;
        uint32_t aBase = sA + ((wm * 64 + (lane & 15)) * 72 + (lane >> 4) * 8) * 2;
        uint32_t bBase = sB + ((wn * 64 + (lane & 7) + (lane >> 4) * 8) * 72 +
                               ((lane >> 3) & 1) * 8) * 2;

        uint32_t af0[4][4], bf0[4][4], af1[4][4], bf1[4][4];
        LOAD_FRAGS(af0, bf0, aBase, bBase, 0);
        LOAD_FRAGS(af1, bf1, aBase, bBase, 16);
        DO_MMAS(d, af0, bf0);
        LOAD_FRAGS(af0, bf0, aBase, bBase, 32);
        DO_MMAS(d, af1, bf1);
        LOAD_FRAGS(af1, bf1, aBase, bBase, 48);
        DO_MMAS(d, af0, bf0);
        DO_MMAS(d, af1, bf1);
    }

    // epilogue: bias + fp16 scatter to ebuf
    const float* bb = b2 + e * HDIM + col0;
#pragma unroll
    for (int mi = 0; mi < 4; mi++) {
        int rbase = wm * 64 + mi * 16 + (lane >> 2);
#pragma unroll
        for (int h = 0; h < 2; h++) {
            int rl = rbase + 8 * h;
            int a = s_asn[rl];
            if (a >= 0) {
                __half* dst = g_ebuf + (size_t)a * HDIM + col0;
#pragma unroll
                for (int nt = 0; nt < 8; nt++) {
                    int cl = wn * 64 + nt * 8 + (lane & 3) * 2;
                    *(__half2*)(dst + cl) =
                        __floats2half2_rn(d[mi][nt][2 * h]     + bb[cl],
                                          d[mi][nt][2 * h + 1] + bb[cl + 1]);
                }
            }
        }
    }
}

// ---------------- combine: out[t] = sum_k w[t][k] * ebuf[t*4+k] ---------------------
__global__ void combine_kernel(float* __restrict__ out) {
    const float* ew = out + (size_t)NTOK * HDIM;
    int stride = gridDim.x * blockDim.x;
    int n4 = NTOK * HDIM / 4;
    for (int v = blockIdx.x * blockDim.x + threadIdx.x; v < n4; v += stride) {
        int t  = v >> 8;
        int hc = v & 255;
        float w0 = ew[t * 4 + 0], w1v = ew[t * 4 + 1];
        float w2v = ew[t * 4 + 2], w3 = ew[t * 4 + 3];
        const __half* eb = g_ebuf + (size_t)t * 4 * HDIM + hc * 4;
        __half2 a0 = *(const __half2*)(eb);
        __half2 a1 = *(const __half2*)(eb + 2);
        __half2 b0 = *(const __half2*)(eb + HDIM);
        __half2 b1 = *(const __half2*)(eb + HDIM + 2);
        __half2 c0 = *(const __half2*)(eb + 2 * HDIM);
        __half2 c1 = *(const __half2*)(eb + 2 * HDIM + 2);
        __half2 d0 = *(const __half2*)(eb + 3 * HDIM);
        __half2 d1 = *(const __half2*)(eb + 3 * HDIM + 2);
        float2 fa0 = __half22float2(a0), fa1 = __half22float2(a1);
        float2 fb0 = __half22float2(b0), fb1 = __half22float2(b1);
        float2 fc0 = __half22float2(c0), fc1 = __half22float2(c1);
        float2 fd0 = __half22float2(d0), fd1 = __half22float2(d1);
        float4 o;
        o.x = w0 * fa0.x + w1v * fb0.x + w2v * fc0.x + w3 * fd0.x;
        o.y = w0 * fa0.y + w1v * fb0.y + w2v * fc0.y + w3 * fd0.y;
        o.z = w0 * fa1.x + w1v * fb1.x + w2v * fc1.x + w3 * fd1.x;
        o.w = w0 * fa1.y + w1v * fb1.y + w2v * fc1.y + w3 * fd1.y;
        ((float4*)out)[v] = o;
    }
}

// ---------------- launch ------------------------------------------------------------
extern "C" void kernel_launch(void* const* d_in, const int* in_sizes, int n_in,
                              void* d_out, int out_size) {
    const float* x  = (const float*)d_in[0];
    const float* rw = (const float*)d_in[1];
    const float* rb = (const float*)d_in[2];
    const float* w1 = (const float*)d_in[3];
    const float* b1 = (const float*)d_in[4];
    const float* w2 = (const float*)d_in[5];
    const float* b2 = (const float*)d_in[6];
    float* out = (float*)d_out;

    cudaFuncSetAttribute(gemm1_kernel, cudaFuncAttributeMaxDynamicSharedMemorySize, SMEM_TOTAL);
    cudaFuncSetAttribute(gemm2_kernel, cudaFuncAttributeMaxDynamicSharedMemorySize, SMEM_TOTAL);

    __half* w1h; cudaGetSymbolAddress((void**)&w1h, g_w1h);
    __half* w2h; cudaGetSymbolAddress((void**)&w2h, g_w2h);
    cvt_t_kernel<<<dim3(GUDIM / 32, HDIM / 32, NEXP), dim3(32, 8)>>>(w1, w1h, HDIM, GUDIM);
    cvt_t_kernel<<<dim3(HDIM / 32, IDIM / 32, NEXP), dim3(32, 8)>>>(w2, w2h, IDIM, HDIM);

    xr_kernel<<<NTOK / 8, 256>>>(x, rw, rb, out + (size_t)NTOK * HDIM);

    gemm1_kernel<<<dim3(GUDIM / NT, NTOK / MT, NEXP), 128, SMEM_TOTAL>>>(b1);
    gemm2_kernel<<<dim3(HDIM  / NT, NTOK / MT, NEXP), 128, SMEM_TOTAL>>>(b2);

    combine_kernel<<<2048, 256>>>(out);
}

// round 16
// speedup vs baseline: 1.0523x; 1.0309x over previous
#include <cuda_runtime.h>
#include <cuda_fp16.h>
#include <cstdint>
#include <math.h>

#define NTOK  4096
#define HDIM  1024
#define IDIM  1024
#define NEXP  8
#define TOPK  4
#define GUDIM 2048

#define MT 128
#define NT 128
#define KT 64
#define NCHUNK 16

#define FB_TILE  (128 * 72 * 2)          // 18432 B
#define FB_STAGE (2 * FB_TILE)           // 36864 B
#define SMEM_TOTAL (1024 + 2 * FB_STAGE) // 74752 B -> 3 CTAs/SM (224256 <= 228KB)

// ---------------- device scratch ----------------------------------------------------
__device__ __align__(16) __half g_xh [(size_t)NTOK * HDIM];
__device__ __align__(16) __half g_w1h[(size_t)NEXP * GUDIM * HDIM];   // [e][n][k]
__device__ __align__(16) __half g_w2h[(size_t)NEXP * HDIM * IDIM];    // [e][n][k]
__device__ __align__(16) __half g_act[(size_t)NEXP * NTOK * IDIM];
__device__ __align__(16) __half g_ebuf[(size_t)NTOK * TOPK * HDIM];   // 32 MB fp16
__device__ int g_count[NEXP];
__device__ int g_assign[NEXP * NTOK];

// ---------------- helpers -----------------------------------------------------------
__device__ __forceinline__ uint32_t smem_u32(const void* p) {
    uint32_t a;
    asm("{ .reg .u64 t; cvta.to.shared.u64 t, %1; cvt.u32.u64 %0, t; }" : "=r"(a) : "l"(p));
    return a;
}

#define CPA16(dst, src)       asm volatile("cp.async.cg.shared.global [%0], [%1], 16;"     :: "r"(dst), "l"(src))
#define CPA16P(dst, src, sz)  asm volatile("cp.async.cg.shared.global [%0], [%1], 16, %2;" :: "r"(dst), "l"(src), "r"(sz))
#define CPA_COMMIT()          asm volatile("cp.async.commit_group;" ::: "memory")
#define CPA_WAIT(n)           asm volatile("cp.async.wait_group %0;" :: "n"(n) : "memory")

__device__ __forceinline__ void ldsm4(uint32_t& r0, uint32_t& r1, uint32_t& r2, uint32_t& r3,
                                      uint32_t addr) {
    asm volatile("ldmatrix.sync.aligned.m8n8.x4.shared.b16 {%0,%1,%2,%3}, [%4];"
                 : "=r"(r0), "=r"(r1), "=r"(r2), "=r"(r3) : "r"(addr));
}
__device__ __forceinline__ void mma16816(float* d, const uint32_t* a, uint32_t b0, uint32_t b1) {
    asm volatile("mma.sync.aligned.m16n8k16.row.col.f32.f16.f16.f32 "
                 "{%0,%1,%2,%3},{%4,%5,%6,%7},{%8,%9},{%0,%1,%2,%3};"
                 : "+f"(d[0]), "+f"(d[1]), "+f"(d[2]), "+f"(d[3])
                 : "r"(a[0]), "r"(a[1]), "r"(a[2]), "r"(a[3]), "r"(b0), "r"(b1));
}

// ---------------- utility kernels ---------------------------------------------------
// transpose-convert: s [z][K][N] fp32 -> d [z][N][K] fp16 (also zeroes g_count)
__global__ void cvt_t_kernel(const float* __restrict__ s, __half* __restrict__ d,
                             int K, int N) {
    __shared__ float t[32][33];
    int tx = threadIdx.x, ty = threadIdx.y;
    if (blockIdx.x == 0 && blockIdx.y == 0 && blockIdx.z == 0 && ty == 0 && tx < NEXP)
        g_count[tx] = 0;
    int n0 = blockIdx.x * 32, k0 = blockIdx.y * 32, z = blockIdx.z;
    const float* sp = s + (size_t)z * K * N;
    __half* dp = d + (size_t)z * K * N;
#pragma unroll
    for (int i = 0; i < 32; i += 8)
        t[ty + i][tx] = sp[(size_t)(k0 + ty + i) * N + n0 + tx];
    __syncthreads();
    int id = ty * 32 + tx;
#pragma unroll
    for (int j = 0; j < 2; j++) {
        int v = id + j * 256;
        int r = v >> 4;
        int c = v & 15;
        __half2 h = __floats2half2_rn(t[c * 2][r], t[c * 2 + 1][r]);
        *(__half2*)(dp + (size_t)(n0 + r) * K + k0 + c * 2) = h;
    }
}

// ---------------- fused x-convert + router: 1 warp/token ----------------------------
__global__ void xr_kernel(const float* __restrict__ x,
                          const float* __restrict__ rw,
                          const float* __restrict__ rb,
                          float* __restrict__ ew_out) {
    int warp = (blockIdx.x * blockDim.x + threadIdx.x) >> 5;
    int lane = threadIdx.x & 31;
    if (warp >= NTOK) return;
    const float4* xr = (const float4*)(x + (size_t)warp * HDIM);
    __half2* xh = (__half2*)(g_xh + (size_t)warp * HDIM);

    float acc[NEXP];
#pragma unroll
    for (int e = 0; e < NEXP; e++) acc[e] = 0.f;

#pragma unroll
    for (int it = 0; it < 8; it++) {
        float4 xv = xr[lane + it * 32];
        xh[(lane + it * 32) * 2]     = __floats2half2_rn(xv.x, xv.y);
        xh[(lane + it * 32) * 2 + 1] = __floats2half2_rn(xv.z, xv.w);
#pragma unroll
        for (int e = 0; e < NEXP; e++) {
            float4 rv = ((const float4*)(rw + e * HDIM))[lane + it * 32];
            acc[e] += xv.x * rv.x + xv.y * rv.y + xv.z * rv.z + xv.w * rv.w;
        }
    }
#pragma unroll
    for (int e = 0; e < NEXP; e++) {
#pragma unroll
        for (int off = 16; off; off >>= 1)
            acc[e] += __shfl_xor_sync(0xffffffffu, acc[e], off);
    }
    if (lane == 0) {
        float lg[NEXP];
#pragma unroll
        for (int e = 0; e < NEXP; e++) lg[e] = acc[e] + rb[e];
        int idx[TOPK]; float val[TOPK]; bool used[NEXP];
#pragma unroll
        for (int e = 0; e < NEXP; e++) used[e] = false;
        for (int k = 0; k < TOPK; k++) {
            float best = -INFINITY; int bi = 0;
            for (int e = 0; e < NEXP; e++)
                if (!used[e] && lg[e] > best) { best = lg[e]; bi = e; }
            used[bi] = true; idx[k] = bi; val[k] = best;
        }
        float m = val[0], s = 0.f, w[TOPK];
        for (int k = 0; k < TOPK; k++) { w[k] = expf(val[k] - m); s += w[k]; }
        float inv = 1.f / s;
        for (int k = 0; k < TOPK; k++) {
            w[k] *= inv;
            ew_out[warp * TOPK + k] = w[k];
            int p = atomicAdd(&g_count[idx[k]], 1);
            g_assign[idx[k] * NTOK + p] = warp * 4 + k;
        }
    }
}

// ====================================================================================
// GEMM1: act = SwiGLU(gather(x) @ w1^T + b1)   (128 thr, 4 warps, 3 CTAs/SM)
// ====================================================================================
__global__ __launch_bounds__(128, 3)
void gemm1_kernel(const float* __restrict__ b1) {
    extern __shared__ char smem[];
    const int e    = blockIdx.z;
    const int cnt  = g_count[e];
    const int row0 = blockIdx.y * MT;
    if (row0 >= cnt) return;
    const int col0 = blockIdx.x * NT;
    const int tid = threadIdx.x, lane = tid & 31, wid = tid >> 5;
    const int wm = wid >> 1, wn = wid & 1;
    uint32_t sb = smem_u32(smem);
    int* s_tok = (int*)smem;

    {
        int r = row0 + tid;
        s_tok[tid] = (r < cnt) ? (g_assign[e * NTOK + r] >> 2) : -1;
    }
    __syncthreads();

    float d[4][8][4];
#pragma unroll
    for (int mi = 0; mi < 4; mi++)
#pragma unroll
        for (int nt = 0; nt < 8; nt++)
#pragma unroll
            for (int r = 0; r < 4; r++) d[mi][nt][r] = 0.f;

    const __half* Bb = g_w1h + ((size_t)e * GUDIM + col0) * HDIM;
    const int lr = tid >> 3, lc = tid & 7;

    auto issue = [&](int cidx) {
        int p = cidx & 1, kt = cidx * KT;
        uint32_t a0 = sb + 1024 + p * FB_STAGE;
        uint32_t b0 = a0 + FB_TILE;
#pragma unroll
        for (int i = 0; i < 8; i++) {
            int r = lr + i * 16;
            int tok = s_tok[r];
            CPA16P(a0 + (r * 72 + lc * 8) * 2,
                   g_xh + (size_t)(tok < 0 ? 0 : tok) * HDIM + kt + lc * 8,
                   (tok >= 0) ? 16 : 0);
            CPA16(b0 + (r * 72 + lc * 8) * 2, Bb + (size_t)r * HDIM + kt + lc * 8);
        }
        CPA_COMMIT();
    };

    issue(0);
    for (int cc = 0; cc < NCHUNK; cc++) {
        int p = cc & 1;
        CPA_WAIT(0);
        __syncthreads();
        if (cc + 1 < NCHUNK) issue(cc + 1);
        uint32_t sA = sb + 1024 + p * FB_STAGE;
        uint32_t sB = sA + FB_TILE;
        uint32_t aBase = sA + ((wm * 64 + (lane & 15)) * 72 + (lane >> 4) * 8) * 2;
        uint32_t bBase = sB + ((wn * 64 + (lane & 7) + (lane >> 4) * 8) * 72 +
                               ((lane >> 3) & 1) * 8) * 2;
#pragma unroll
        for (int kk = 0; kk < KT; kk += 16) {
            uint32_t a[4][4], b[4][4];
#pragma unroll
            for (int mi = 0; mi < 4; mi++)
                ldsm4(a[mi][0], a[mi][1], a[mi][2], a[mi][3],
                      aBase + (mi * 16 * 72 + kk) * 2);
#pragma unroll
            for (int g = 0; g < 4; g++)
                ldsm4(b[g][0], b[g][1], b[g][2], b[g][3],
                      bBase + (g * 16 * 72 + kk) * 2);
#pragma unroll
            for (int mi = 0; mi < 4; mi++)
#pragma unroll
                for (int g = 0; g < 4; g++) {
                    mma16816(d[mi][2 * g],     a[mi], b[g][0], b[g][1]);
                    mma16816(d[mi][2 * g + 1], a[mi], b[g][2], b[g][3]);
                }
        }
    }
    __syncthreads();   // buffers become staging area

    // epilogue: SwiGLU from register pairs; stage fp16 [128 rows][64 cols] pitch 72
    __half* st_h = (__half*)(smem + 1024);
    const float* bb = b1 + e * GUDIM + col0;
#pragma unroll
    for (int mi = 0; mi < 4; mi++) {
        int rbase = wm * 64 + mi * 16 + (lane >> 2);
#pragma unroll
        for (int nt = 0; nt < 8; nt++) {
            int gcl = wn * 64 + nt * 8 + (lane & 3) * 2;
            float bg = bb[gcl], bu = bb[gcl + 1];
            int acl = (gcl >> 1);
#pragma unroll
            for (int h = 0; h < 2; h++) {
                float g = d[mi][nt][2 * h]     + bg;
                float u = d[mi][nt][2 * h + 1] + bu;
                g = fminf(g, 7.0f);
                u = fminf(fmaxf(u, -7.0f), 7.0f);
                float glu = g / (1.0f + expf(-1.702f * g));
                st_h[(rbase + 8 * h) * 72 + acl] = __float2half((u + 1.0f) * glu);
            }
        }
    }
    __syncthreads();
    {
        int rg = row0 + tid;
        if (rg < cnt) {
            __half* dst = g_act + ((size_t)e * NTOK + rg) * IDIM + (col0 >> 1);
            const __half* src = st_h + tid * 72;
#pragma unroll
            for (int j = 0; j < 8; j++)
                *(int4*)(dst + j * 8) = *(const int4*)(src + j * 8);
        }
    }
}

// ====================================================================================
// GEMM2: ebuf[assign] = fp16(act @ w2^T + b2)   (128 thr, 4 warps, 3 CTAs/SM)
// ====================================================================================
__global__ __launch_bounds__(128, 3)
void gemm2_kernel(const float* __restrict__ b2) {
    extern __shared__ char smem[];
    const int e    = blockIdx.z;
    const int cnt  = g_count[e];
    const int row0 = blockIdx.y * MT;
    if (row0 >= cnt) return;
    const int col0 = blockIdx.x * NT;
    const int tid = threadIdx.x, lane = tid & 31, wid = tid >> 5;
    const int wm = wid >> 1, wn = wid & 1;
    uint32_t sb = smem_u32(smem);
    int* s_asn = (int*)smem;

    {
        int r = row0 + tid;
        s_asn[tid] = (r < cnt) ? g_assign[e * NTOK + r] : -1;
    }
    __syncthreads();

    float d[4][8][4];
#pragma unroll
    for (int mi = 0; mi < 4; mi++)
#pragma unroll
        for (int nt = 0; nt < 8; nt++)
#pragma unroll
            for (int r = 0; r < 4; r++) d[mi][nt][r] = 0.f;

    const __half* Ab = g_act + ((size_t)e * NTOK + row0) * IDIM;
    const __half* Bb = g_w2h + (size_t)e * HDIM * IDIM + (size_t)col0 * IDIM;
    const int lr = tid >> 3, lc = tid & 7;

    auto issue = [&](int cidx) {
        int p = cidx & 1, kt = cidx * KT;
        uint32_t a0 = sb + 1024 + p * FB_STAGE;
        uint32_t b0 = a0 + FB_TILE;
#pragma unroll
        for (int i = 0; i < 8; i++) {
            int r = lr + i * 16;
            int ok = (s_asn[r] >= 0) ? 16 : 0;
            CPA16P(a0 + (r * 72 + lc * 8) * 2, Ab + (size_t)r * IDIM + kt + lc * 8, ok);
            CPA16(b0 + (r * 72 + lc * 8) * 2, Bb + (size_t)r * IDIM + kt + lc * 8);
        }
        CPA_COMMIT();
    };

    issue(0);
    for (int cc = 0; cc < NCHUNK; cc++) {
        int p = cc & 1;
        CPA_WAIT(0);
        __syncthreads();
        if (cc + 1 < NCHUNK) issue(cc + 1);
        uint32_t sA = sb + 1024 + p * FB_STAGE;
        uint32_t sB = sA + FB_TILE;
        uint32_t aBase = sA + ((wm * 64 + (lane & 15)) * 72 + (lane >> 4) * 8) * 2;
        uint32_t bBase = sB + ((wn * 64 + (lane & 7) + (lane >> 4) * 8) * 72 +
                               ((lane >> 3) & 1) * 8) * 2;
#pragma unroll
        for (int kk = 0; kk < KT; kk += 16) {
            uint32_t a[4][4], b[4][4];
#pragma unroll
            for (int mi = 0; mi < 4; mi++)
                ldsm4(a[mi][0], a[mi][1], a[mi][2], a[mi][3],
                      aBase + (mi * 16 * 72 + kk) * 2);
#pragma unroll
            for (int g = 0; g < 4; g++)
                ldsm4(b[g][0], b[g][1], b[g][2], b[g][3],
                      bBase + (g * 16 * 72 + kk) * 2);
#pragma unroll
            for (int mi = 0; mi < 4; mi++)
#pragma unroll
                for (int g = 0; g < 4; g++) {
                    mma16816(d[mi][2 * g],     a[mi], b[g][0], b[g][1]);
                    mma16816(d[mi][2 * g + 1], a[mi], b[g][2], b[g][3]);
                }
        }
    }

    // epilogue: bias + fp16 scatter to ebuf
    const float* bb = b2 + e * HDIM + col0;
#pragma unroll
    for (int mi = 0; mi < 4; mi++) {
        int rbase = wm * 64 + mi * 16 + (lane >> 2);
#pragma unroll
        for (int h = 0; h < 2; h++) {
            int rl = rbase + 8 * h;
            int a = s_asn[rl];
            if (a >= 0) {
                __half* dst = g_ebuf + (size_t)a * HDIM + col0;
#pragma unroll
                for (int nt = 0; nt < 8; nt++) {
                    int cl = wn * 64 + nt * 8 + (lane & 3) * 2;
                    *(__half2*)(dst + cl) =
                        __floats2half2_rn(d[mi][nt][2 * h]     + bb[cl],
                                          d[mi][nt][2 * h + 1] + bb[cl + 1]);
                }
            }
        }
    }
}

// ---------------- combine: out[t] = sum_k w[t][k] * ebuf[t*4+k] ---------------------
__global__ void combine_kernel(float* __restrict__ out) {
    const float* ew = out + (size_t)NTOK * HDIM;
    int stride = gridDim.x * blockDim.x;
    int n4 = NTOK * HDIM / 4;
    for (int v = blockIdx.x * blockDim.x + threadIdx.x; v < n4; v += stride) {
        int t  = v >> 8;
        int hc = v & 255;
        float w0 = ew[t * 4 + 0], w1v = ew[t * 4 + 1];
        float w2v = ew[t * 4 + 2], w3 = ew[t * 4 + 3];
        const __half* eb = g_ebuf + (size_t)t * 4 * HDIM + hc * 4;
        __half2 a0 = *(const __half2*)(eb);
        __half2 a1 = *(const __half2*)(eb + 2);
        __half2 b0 = *(const __half2*)(eb + HDIM);
        __half2 b1 = *(const __half2*)(eb + HDIM + 2);
        __half2 c0 = *(const __half2*)(eb + 2 * HDIM);
        __half2 c1 = *(const __half2*)(eb + 2 * HDIM + 2);
        __half2 d0 = *(const __half2*)(eb + 3 * HDIM);
        __half2 d1 = *(const __half2*)(eb + 3 * HDIM + 2);
        float2 fa0 = __half22float2(a0), fa1 = __half22float2(a1);
        float2 fb0 = __half22float2(b0), fb1 = __half22float2(b1);
        float2 fc0 = __half22float2(c0), fc1 = __half22float2(c1);
        float2 fd0 = __half22float2(d0), fd1 = __half22float2(d1);
        float4 o;
        o.x = w0 * fa0.x + w1v * fb0.x + w2v * fc0.x + w3 * fd0.x;
        o.y = w0 * fa0.y + w1v * fb0.y + w2v * fc0.y + w3 * fd0.y;
        o.z = w0 * fa1.x + w1v * fb1.x + w2v * fc1.x + w3 * fd1.x;
        o.w = w0 * fa1.y + w1v * fb1.y + w2v * fc1.y + w3 * fd1.y;
        ((float4*)out)[v] = o;
    }
}

// ---------------- launch ------------------------------------------------------------
extern "C" void kernel_launch(void* const* d_in, const int* in_sizes, int n_in,
                              void* d_out, int out_size) {
    const float* x  = (const float*)d_in[0];
    const float* rw = (const float*)d_in[1];
    const float* rb = (const float*)d_in[2];
    const float* w1 = (const float*)d_in[3];
    const float* b1 = (const float*)d_in[4];
    const float* w2 = (const float*)d_in[5];
    const float* b2 = (const float*)d_in[6];
    float* out = (float*)d_out;

    cudaFuncSetAttribute(gemm1_kernel, cudaFuncAttributeMaxDynamicSharedMemorySize, SMEM_TOTAL);
    cudaFuncSetAttribute(gemm2_kernel, cudaFuncAttributeMaxDynamicSharedMemorySize, SMEM_TOTAL);

    __half* w1h; cudaGetSymbolAddress((void**)&w1h, g_w1h);
    __half* w2h; cudaGetSymbolAddress((void**)&w2h, g_w2h);
    cvt_t_kernel<<<dim3(GUDIM / 32, HDIM / 32, NEXP), dim3(32, 8)>>>(w1, w1h, HDIM, GUDIM);
    cvt_t_kernel<<<dim3(HDIM / 32, IDIM / 32, NEXP), dim3(32, 8)>>>(w2, w2h, IDIM, HDIM);

    xr_kernel<<<NTOK / 8, 256>>>(x, rw, rb, out + (size_t)NTOK * HDIM);

    gemm1_kernel<<<dim3(GUDIM / NT, NTOK / MT, NEXP), 128, SMEM_TOTAL>>>(b1);
    gemm2_kernel<<<dim3(HDIM  / NT, NTOK / MT, NEXP), 128, SMEM_TOTAL>>>(b2);

    combine_kernel<<<2048, 256>>>(out);
}